// round 11
// baseline (speedup 1.0000x reference)
#include <cuda_runtime.h>
#include <cuda_bf16.h>
#include <cstdint>

// 3-layer GRU (r,z,n), B=128, T=512, H=512, fp32 — bf16 hi/lo mma.sync, v5.
// Wavefront: tick k -> layer l computes t = k - l; one grid barrier per tick.
// 96 CTAs = 3 layers x 16 col-tiles x 2 batch halves.
// v5: warp specialization. 18 warps: 0-15 MMA consumers (4Mx4N, D[16,128]),
// 16-17 cp.async producers. 4-slot smem ring with mbarrier full/empty pairs;
// consumers never issue LDGSTS / bar.sync in the mainloop.
// D[64,128] = sum over K=1024 of a_hi*w_hi + a_lo*w_hi + a_hi*w_lo.

#define Bv 128
#define Tv 512
#define Hv 512
#define NLAYER 3
#define CPL 16
#define NCTA 96
#define BLK 576
#define NTICK (Tv + 2)
#define KREAL 1024
#define KCH 64
#define NCHUNK (KREAL / KCH)   // 16
#define AROWB 144
#define OFF_ALO 9216           // 64*144
#define OFF_WHI 18432
#define STAGE_BYTES 55296
#define SMEM_TOTAL (1024 + 4 * STAGE_BYTES)

__device__ __nv_bfloat16 g_B[NLAYER][CPL][2][128][KREAL];  // [hl][n][k]
__device__ __nv_bfloat16 g_A[NLAYER][2][2][Bv][KREAL];     // [parity][hl][m][k]
__device__ unsigned g_count = 0;
__device__ unsigned g_phase = 0;

__device__ __forceinline__ uint32_t smem_u32(const void* p) {
    uint32_t a;
    asm("{ .reg .u64 t; cvta.to.shared.u64 t, %1; cvt.u32.u64 %0, t; }" : "=r"(a) : "l"(p));
    return a;
}
__device__ __forceinline__ void cp16(uint32_t s, const void* g) {
    asm volatile("cp.async.cg.shared.global [%0], [%1], 16;" :: "r"(s), "l"(g));
}
__device__ __forceinline__ float sigf(float x) { return 1.f / (1.f + __expf(-x)); }
__device__ __forceinline__ float tanh_fast(float x) {
    x = fminf(fmaxf(x, -15.f), 15.f);
    float t = __expf(2.f * x);
    return (t - 1.f) / (t + 1.f);
}
__device__ __forceinline__ void gsync(unsigned target) {
    __syncthreads();
    if (threadIdx.x == 0) {
        __threadfence();
        unsigned a = atomicAdd(&g_count, 1u);
        if (a == NCTA - 1) {
            g_count = 0u;
            __threadfence();
            atomicAdd(&g_phase, 1u);
        } else {
            while (*((volatile unsigned*)&g_phase) < target) __nanosleep(32);
        }
    }
    __syncthreads();
}

#define MBAR_INIT(a, n) asm volatile("mbarrier.init.shared.b64 [%0], %1;" :: "r"(a), "r"(n) : "memory")
#define MBAR_ARRIVE(a)  asm volatile("mbarrier.arrive.shared.b64 _, [%0];" :: "r"(a) : "memory")
#define MBAR_WAIT(a, par) do { \
    uint32_t _m = (a), _p = (par), _d; \
    asm volatile("{ .reg .pred p; mbarrier.try_wait.parity.acquire.cta.shared::cta.b64 p, [%1], %2; selp.b32 %0,1,0,p; }" \
                 : "=r"(_d) : "r"(_m), "r"(_p) : "memory"); \
    if (!_d) { asm volatile("{ .reg .pred P1; WL_%=: mbarrier.try_wait.parity.acquire.cta.shared::cta.b64 P1, [%0], %1, 0x989680; @P1 bra.uni WD_%=; bra.uni WL_%=; WD_%=: }" \
                            :: "r"(_m), "r"(_p) : "memory"); } \
} while (0)

#define MMA16816(d, a, b0, b1) \
    asm volatile("mma.sync.aligned.m16n8k16.row.col.f32.bf16.bf16.f32 " \
        "{%0,%1,%2,%3}, {%4,%5,%6,%7}, {%8,%9}, {%0,%1,%2,%3};" \
        : "+f"((d)[0]), "+f"((d)[1]), "+f"((d)[2]), "+f"((d)[3]) \
        : "r"((a)[0]), "r"((a)[1]), "r"((a)[2]), "r"((a)[3]), \
          "r"(b0), "r"(b1))

#define LDMX4(r, a) \
    asm volatile("ldmatrix.sync.aligned.m8n8.x4.shared.b16 {%0,%1,%2,%3}, [%4];" \
        : "=r"((r)[0]), "=r"((r)[1]), "=r"((r)[2]), "=r"((r)[3]) : "r"(a))

// ---------------- prep ----------------
__global__ void gru_prep(const float* __restrict__ x,
    const float* __restrict__ Wih0, const float* __restrict__ Whh0,
    const float* __restrict__ Wih1, const float* __restrict__ Whh1,
    const float* __restrict__ Wih2, const float* __restrict__ Whh2)
{
    const float* WI[3] = {Wih0, Wih1, Wih2};
    const float* WH[3] = {Whh0, Whh1, Whh2};
    const long gsz = (long)gridDim.x * blockDim.x;
    const long gid = (long)blockIdx.x * blockDim.x + threadIdx.x;

    const long BTOT = (long)NLAYER * CPL * 2 * 128 * KREAL;
    for (long idx = gid; idx < BTOT; idx += gsz) {
        int k   = (int)(idx & (KREAL - 1));
        long r0 = idx >> 10;
        int n   = (int)(r0 & 127);
        long r1 = r0 >> 7;
        int hl  = (int)(r1 & 1);
        long r2 = r1 >> 1;
        int li  = (int)(r2 % CPL);
        int l   = (int)(r2 / CPL);
        int gate = n >> 5, u = n & 31, j = li * 32 + u;
        int half = k >> 9, kk = k & 511;
        float wv = 0.f;
        if (half == 0) {
            if (gate < 3) wv = WI[l][(size_t)(gate * Hv + j) * Hv + kk];
        } else {
            if (gate == 0)      wv = WH[l][(size_t)(0 * Hv + j) * Hv + kk];
            else if (gate == 1) wv = WH[l][(size_t)(1 * Hv + j) * Hv + kk];
            else if (gate == 3) wv = WH[l][(size_t)(2 * Hv + j) * Hv + kk];
        }
        __nv_bfloat16 hi = __float2bfloat16(wv);
        (&g_B[0][0][0][0][0])[idx] = (hl == 0) ? hi
            : __float2bfloat16(wv - __bfloat162float(hi));
    }
    const long ATOT = (long)NLAYER * 2 * 2 * Bv * KREAL;
    for (long idx = gid; idx < ATOT; idx += gsz) {
        int k = (int)(idx & (KREAL - 1));
        long r0 = idx >> 10;
        int m = (int)(r0 & 127);
        long r1 = r0 >> 7;
        int hl = (int)(r1 & 1);
        int p  = (int)((r1 >> 1) & 1);
        int l  = (int)(r1 >> 2);
        __nv_bfloat16 out = __float2bfloat16(0.f);
        if (l == 0 && p == 1 && k < 512) {
            float v = x[((size_t)m * Tv) * Hv + k];
            __nv_bfloat16 hi = __float2bfloat16(v);
            out = (hl == 0) ? hi : __float2bfloat16(v - __bfloat162float(hi));
        }
        (&g_A[0][0][0][0][0])[idx] = out;
    }
}

// ---------------- main persistent HMMA kernel ----------------
__global__ void __launch_bounds__(BLK, 1) gru_tc(
    const float* __restrict__ x,
    const float* __restrict__ bih0, const float* __restrict__ bhh0,
    const float* __restrict__ bih1, const float* __restrict__ bhh1,
    const float* __restrict__ bih2, const float* __restrict__ bhh2,
    float* __restrict__ y)
{
    extern __shared__ char smem[];
    const uint32_t smb = smem_u32(smem);
    const uint32_t sm0 = smb + 1024;
    // mbarriers: full[4] @ smb+0..31, empty[4] @ smb+32..63; bias @ +128
    const int tid  = threadIdx.x;
    const int lane = tid & 31;
    const int wid  = tid >> 5;
    const int l     = blockIdx.x >> 5;
    const int li    = (blockIdx.x >> 1) & 15;
    const int mhalf = blockIdx.x & 1;
    const int J0    = li * 32;

    const float* bihL = (l == 0) ? bih0 : (l == 1) ? bih1 : bih2;
    const float* bhhL = (l == 0) ? bhh0 : (l == 1) ? bhh1 : bhh2;

    float* sb = (float*)(smem + 128);
    if (tid == 0) {
#pragma unroll
        for (int s = 0; s < 4; ++s) {
            MBAR_INIT(smb + s * 8, 2);        // full: 2 producer warps
            MBAR_INIT(smb + 32 + s * 8, 16);  // empty: 16 consumer warps
        }
    }
    if (tid < 32) {
        int j = J0 + tid;
        sb[tid]      = bihL[0 * Hv + j] + bhhL[0 * Hv + j];
        sb[32 + tid] = bihL[1 * Hv + j] + bhhL[1 * Hv + j];
        sb[64 + tid] = bihL[2 * Hv + j];
        sb[96 + tid] = bhhL[2 * Hv + j];
    }
    __syncthreads();

    const __nv_bfloat16* Bg = &g_B[l][li][0][0][0];
    const unsigned base = *((volatile unsigned*)&g_phase);

    if (wid >= 16) {
        // ================= PRODUCER warps (2) =================
        const int p = wid - 16;           // 0,1
        const int lane64 = p * 32 + lane;
        int eStage = 0, ePhase = 1;       // empty-cursor (starts "empty")
#pragma unroll 1
        for (int k = 0; k < NTICK; ++k) {
            const int t = k - l;
            if (t >= 0 && t < Tv) {
                const int rp = (k + 1) & 1;
                const char* Ag = (const char*)&g_A[l][rp][0][0][0];
                const char* Bgc = (const char*)Bg;
#pragma unroll 1
                for (int c = 0; c < NCHUNK; ++c) {
                    MBAR_WAIT(smb + 32 + (uint32_t)eStage * 8, ePhase);
                    const uint32_t buf = sm0 + (uint32_t)(c & 3) * STAGE_BYTES;
                    const char* gaB = Ag + (size_t)c * (KCH * 2);
                    const char* gbB = Bgc + (size_t)c * (KCH * 2);
#pragma unroll
                    for (int j2 = 0; j2 < 48; ++j2) {
                        int i = lane64 + j2 * 64;    // 0..3071
                        int c16 = i & 7;
                        int rl = i >> 3;             // 0..383
                        uint32_t dst; const char* src;
                        if (rl < 128) {              // A planes
                            int hl = rl >> 6, r = rl & 63;
                            dst = buf + (uint32_t)(hl * OFF_ALO + r * AROWB + c16 * 16);
                            src = gaB + ((size_t)hl * 128 + 64 * mhalf + r) * (KREAL * 2)
                                      + c16 * 16;
                        } else {                     // W planes
                            int rb = rl - 128;
                            int hl = rb >> 7, r = rb & 127;
                            dst = buf + (uint32_t)(OFF_WHI + hl * 18432 + r * AROWB + c16 * 16);
                            src = gbB + ((size_t)hl * 128 + r) * (KREAL * 2) + c16 * 16;
                        }
                        cp16(dst, src);
                    }
                    asm volatile("cp.async.commit_group;");
                    if (c >= 2) {
                        asm volatile("cp.async.wait_group 2;");
                        if (lane == 0) MBAR_ARRIVE(smb + (uint32_t)((c - 2) & 3) * 8);
                    }
                    if (++eStage == 4) { eStage = 0; ePhase ^= 1; }
                }
                asm volatile("cp.async.wait_group 1;");
                if (lane == 0) MBAR_ARRIVE(smb + (uint32_t)((NCHUNK - 2) & 3) * 8);
                asm volatile("cp.async.wait_group 0;");
                if (lane == 0) MBAR_ARRIVE(smb + (uint32_t)((NCHUNK - 1) & 3) * 8);
            }
            gsync(base + 1 + k);
        }
        return;
    }

    // ================= CONSUMER warps (16) =================
    const int mw = wid >> 2;            // 0..3
    const int nw = wid & 3;             // 0..3
    const uint32_t aoff = (uint32_t)((16 * mw + (lane & 15)) * AROWB + (lane >> 4) * 16);
    const uint32_t boff0 = (uint32_t)((32 * (lane >> 4) + 8 * nw + (lane & 7)) * AROWB
                                      + ((lane >> 3) & 1) * 16);
    const uint32_t boff1 = boff0 + 64u * AROWB;

    const int u0 = 8 * nw + (lane & 3) * 2;
    const int m0 = 64 * mhalf + 16 * mw + (lane >> 2);
    const int j0 = J0 + u0;
    float hloc[4] = {0.f, 0.f, 0.f, 0.f};
    int fStage = 0, fPhase = 0;         // full-cursor

#pragma unroll 1
    for (int k = 0; k < NTICK; ++k) {
        const int t = k - l;
        const bool active = (t >= 0) && (t < Tv);
        const int wp = k & 1;

        if (active) {
            float2 xm[2];
            if (l == 2) {
                xm[0] = *(const float2*)(x + ((size_t)m0 * Tv + t) * Hv + j0);
                xm[1] = *(const float2*)(x + ((size_t)(m0 + 8) * Tv + t) * Hv + j0);
            }

            float acc[4][4];
#pragma unroll
            for (int g = 0; g < 4; ++g)
#pragma unroll
                for (int e = 0; e < 4; ++e) acc[g][e] = 0.f;

#pragma unroll 1
            for (int c = 0; c < NCHUNK; ++c) {
                MBAR_WAIT(smb + (uint32_t)fStage * 8, fPhase);
                const uint32_t st = sm0 + (uint32_t)(c & 3) * STAGE_BYTES;
#pragma unroll
                for (int ks = 0; ks < KCH / 16; ++ks) {
                    const uint32_t kb = (uint32_t)(ks * 32);
                    uint32_t ahi[4], alo[4];
                    LDMX4(ahi, st + aoff + kb);
                    LDMX4(alo, st + OFF_ALO + aoff + kb);
                    uint32_t wh0[4], wh1[4], wl0[4], wl1[4];
                    LDMX4(wh0, st + OFF_WHI + boff0 + kb);
                    LDMX4(wh1, st + OFF_WHI + boff1 + kb);
                    LDMX4(wl0, st + OFF_WHI + 18432 + boff0 + kb);
                    LDMX4(wl1, st + OFF_WHI + 18432 + boff1 + kb);
                    MMA16816(acc[0], ahi, wh0[0], wh0[1]);
                    MMA16816(acc[1], ahi, wh0[2], wh0[3]);
                    MMA16816(acc[2], ahi, wh1[0], wh1[1]);
                    MMA16816(acc[3], ahi, wh1[2], wh1[3]);
                    MMA16816(acc[0], alo, wh0[0], wh0[1]);
                    MMA16816(acc[1], alo, wh0[2], wh0[3]);
                    MMA16816(acc[2], alo, wh1[0], wh1[1]);
                    MMA16816(acc[3], alo, wh1[2], wh1[3]);
                    MMA16816(acc[0], ahi, wl0[0], wl0[1]);
                    MMA16816(acc[1], ahi, wl0[2], wl0[3]);
                    MMA16816(acc[2], ahi, wl1[0], wl1[1]);
                    MMA16816(acc[3], ahi, wl1[2], wl1[3]);
                }
                __syncwarp();
                if (lane == 0) MBAR_ARRIVE(smb + 32 + (uint32_t)fStage * 8);
                if (++fStage == 4) { fStage = 0; fPhase ^= 1; }
            }

            // ---------- epilogue ----------
#pragma unroll
            for (int rr = 0; rr < 2; ++rr) {
                const int m = m0 + 8 * rr;
                float hv[2];
#pragma unroll
                for (int up = 0; up < 2; ++up) {
                    const int u = u0 + up, e = 2 * rr + up;
                    float r = sigf(acc[0][e] + sb[u]);
                    float z = sigf(acc[1][e] + sb[32 + u]);
                    float n = tanh_fast(acc[2][e] + sb[64 + u]
                                        + r * (acc[3][e] + sb[96 + u]));
                    hv[up] = (1.f - z) * n + z * hloc[rr * 2 + up];
                }
                if (l == 2) {
                    if (xm[rr].x == 0.f) hv[0] = 0.f;
                    if (xm[rr].y == 0.f) hv[1] = 0.f;
                    *(float2*)(y + ((size_t)m * Tv + t) * Hv + j0) =
                        make_float2(hv[0], hv[1]);
                }
                hloc[rr * 2 + 0] = hv[0];
                hloc[rr * 2 + 1] = hv[1];

                __nv_bfloat16 h0 = __float2bfloat16(hv[0]);
                __nv_bfloat16 h1 = __float2bfloat16(hv[1]);
                __nv_bfloat16 L0 = __float2bfloat16(hv[0] - __bfloat162float(h0));
                __nv_bfloat16 L1 = __float2bfloat16(hv[1] - __bfloat162float(h1));
                unsigned hp32 = (unsigned)__bfloat16_as_ushort(h0)
                              | ((unsigned)__bfloat16_as_ushort(h1) << 16);
                unsigned lp32 = (unsigned)__bfloat16_as_ushort(L0)
                              | ((unsigned)__bfloat16_as_ushort(L1) << 16);
                *(unsigned*)&g_A[l][wp][0][m][512 + j0] = hp32;   // self h-half
                *(unsigned*)&g_A[l][wp][1][m][512 + j0] = lp32;
                if (l < 2) {                                      // next-layer x-half
                    *(unsigned*)&g_A[l + 1][wp][0][m][j0] = hp32;
                    *(unsigned*)&g_A[l + 1][wp][1][m][j0] = lp32;
                }
            }
        }

        // layer-0 CTAs stage x_{k+1} into next parity's A0 x-region
        if (l == 0 && (k + 1) < Tv && tid < 256) {
            const int row = tid >> 2;
            const int kc0 = (tid & 3) * 8;
            const int m = 64 * mhalf + row;
            const float* xs = x + ((size_t)m * Tv + (k + 1)) * Hv + 32 * li + kc0;
            unsigned hp[4], lp[4];
#pragma unroll
            for (int q = 0; q < 4; ++q) {
                float v0 = xs[2 * q], v1 = xs[2 * q + 1];
                __nv_bfloat16 h0 = __float2bfloat16(v0);
                __nv_bfloat16 h1 = __float2bfloat16(v1);
                __nv_bfloat16 L0 = __float2bfloat16(v0 - __bfloat162float(h0));
                __nv_bfloat16 L1 = __float2bfloat16(v1 - __bfloat162float(h1));
                hp[q] = (unsigned)__bfloat16_as_ushort(h0)
                      | ((unsigned)__bfloat16_as_ushort(h1) << 16);
                lp[q] = (unsigned)__bfloat16_as_ushort(L0)
                      | ((unsigned)__bfloat16_as_ushort(L1) << 16);
            }
            *(uint4*)&g_A[0][wp][0][m][32 * li + kc0] =
                make_uint4(hp[0], hp[1], hp[2], hp[3]);
            *(uint4*)&g_A[0][wp][1][m][32 * li + kc0] =
                make_uint4(lp[0], lp[1], lp[2], lp[3]);
        }

        gsync(base + 1 + k);
    }
}

extern "C" void kernel_launch(void* const* d_in, const int* in_sizes, int n_in,
                              void* d_out, int out_size) {
    (void)in_sizes; (void)n_in; (void)out_size;
    const float* x = (const float*)d_in[0];
    gru_prep<<<256, 256>>>(x,
        (const float*)d_in[1], (const float*)d_in[2],
        (const float*)d_in[5], (const float*)d_in[6],
        (const float*)d_in[9], (const float*)d_in[10]);
    cudaFuncSetAttribute(gru_tc, cudaFuncAttributeMaxDynamicSharedMemorySize, SMEM_TOTAL);
    gru_tc<<<NCTA, BLK, SMEM_TOTAL>>>(x,
        (const float*)d_in[3],  (const float*)d_in[4],
        (const float*)d_in[7],  (const float*)d_in[8],
        (const float*)d_in[11], (const float*)d_in[12],
        (float*)d_out);
}

// round 12
// speedup vs baseline: 1.5677x; 1.5677x over previous
#include <cuda_runtime.h>
#include <cuda_bf16.h>
#include <cstdint>

// 3-layer GRU (r,z,n), B=128, T=512, H=512, fp32 — bf16 hi/lo mma.sync, v6.
// = R9 (v4) structure + gate-structured sparsity:
//   gate i_n is zero over the h-half of K, h_n zero over the x-half, so
//   x-half chunks (c<8) skip acc[3] MMAs, h-half chunks skip acc[2] MMAs
//   (12 -> 9 MMA per ks, -25% tensor work, bit-identical result), and the
//   corresponding zero W rows are never staged (-25% W traffic).
// Wavefront: tick k -> layer l computes t = k - l; one grid barrier per tick.
// 96 CTAs = 3 layers x 16 col-tiles x 2 batch halves; 16 warps (4Mx4N).
// D[64,128] = sum over K=1024 of a_hi*w_hi + a_lo*w_hi + a_hi*w_lo.
// 4-stage cp.async ring (distance-3), cross-tick W prefetch, h-state in regs.

#define Bv 128
#define Tv 512
#define Hv 512
#define NLAYER 3
#define CPL 16
#define NCTA 96
#define BLK 512
#define NTICK (Tv + 2)
#define KREAL 1024
#define KCH 64
#define NCHUNK (KREAL / KCH)   // 16
#define AROWB 144
#define OFF_ALO 9216           // 64*144
#define OFF_WHI 18432
#define STAGE_BYTES 55296
#define SMEM_TOTAL (512 + 4 * STAGE_BYTES)

__device__ __nv_bfloat16 g_B[NLAYER][CPL][2][128][KREAL];  // [hl][n][k]
__device__ __nv_bfloat16 g_A[NLAYER][2][2][Bv][KREAL];     // [parity][hl][m][k]
__device__ unsigned g_count = 0;
__device__ unsigned g_phase = 0;

__device__ __forceinline__ uint32_t smem_u32(const void* p) {
    uint32_t a;
    asm("{ .reg .u64 t; cvta.to.shared.u64 t, %1; cvt.u32.u64 %0, t; }" : "=r"(a) : "l"(p));
    return a;
}
__device__ __forceinline__ void cp16(uint32_t s, const void* g) {
    asm volatile("cp.async.cg.shared.global [%0], [%1], 16;" :: "r"(s), "l"(g));
}
__device__ __forceinline__ float sigf(float x) { return 1.f / (1.f + __expf(-x)); }
__device__ __forceinline__ float tanh_fast(float x) {
    x = fminf(fmaxf(x, -15.f), 15.f);
    float t = __expf(2.f * x);
    return (t - 1.f) / (t + 1.f);
}
__device__ __forceinline__ void gsync(unsigned target) {
    __syncthreads();
    if (threadIdx.x == 0) {
        __threadfence();
        unsigned a = atomicAdd(&g_count, 1u);
        if (a == NCTA - 1) {
            g_count = 0u;
            __threadfence();
            atomicAdd(&g_phase, 1u);
        } else {
            while (*((volatile unsigned*)&g_phase) < target) __nanosleep(32);
        }
    }
    __syncthreads();
}

#define MMA16816(d, a, b0, b1) \
    asm volatile("mma.sync.aligned.m16n8k16.row.col.f32.bf16.bf16.f32 " \
        "{%0,%1,%2,%3}, {%4,%5,%6,%7}, {%8,%9}, {%0,%1,%2,%3};" \
        : "+f"((d)[0]), "+f"((d)[1]), "+f"((d)[2]), "+f"((d)[3]) \
        : "r"((a)[0]), "r"((a)[1]), "r"((a)[2]), "r"((a)[3]), \
          "r"(b0), "r"(b1))

#define LDMX4(r, a) \
    asm volatile("ldmatrix.sync.aligned.m8n8.x4.shared.b16 {%0,%1,%2,%3}, [%4];" \
        : "=r"((r)[0]), "=r"((r)[1]), "=r"((r)[2]), "=r"((r)[3]) : "r"(a))

// ---------------- prep ----------------
__global__ void gru_prep(const float* __restrict__ x,
    const float* __restrict__ Wih0, const float* __restrict__ Whh0,
    const float* __restrict__ Wih1, const float* __restrict__ Whh1,
    const float* __restrict__ Wih2, const float* __restrict__ Whh2)
{
    const float* WI[3] = {Wih0, Wih1, Wih2};
    const float* WH[3] = {Whh0, Whh1, Whh2};
    const long gsz = (long)gridDim.x * blockDim.x;
    const long gid = (long)blockIdx.x * blockDim.x + threadIdx.x;

    const long BTOT = (long)NLAYER * CPL * 2 * 128 * KREAL;
    for (long idx = gid; idx < BTOT; idx += gsz) {
        int k   = (int)(idx & (KREAL - 1));
        long r0 = idx >> 10;
        int n   = (int)(r0 & 127);
        long r1 = r0 >> 7;
        int hl  = (int)(r1 & 1);
        long r2 = r1 >> 1;
        int li  = (int)(r2 % CPL);
        int l   = (int)(r2 / CPL);
        int gate = n >> 5, u = n & 31, j = li * 32 + u;
        int half = k >> 9, kk = k & 511;
        float wv = 0.f;
        if (half == 0) {
            if (gate < 3) wv = WI[l][(size_t)(gate * Hv + j) * Hv + kk];
        } else {
            if (gate == 0)      wv = WH[l][(size_t)(0 * Hv + j) * Hv + kk];
            else if (gate == 1) wv = WH[l][(size_t)(1 * Hv + j) * Hv + kk];
            else if (gate == 3) wv = WH[l][(size_t)(2 * Hv + j) * Hv + kk];
        }
        __nv_bfloat16 hi = __float2bfloat16(wv);
        (&g_B[0][0][0][0][0])[idx] = (hl == 0) ? hi
            : __float2bfloat16(wv - __bfloat162float(hi));
    }
    const long ATOT = (long)NLAYER * 2 * 2 * Bv * KREAL;
    for (long idx = gid; idx < ATOT; idx += gsz) {
        int k = (int)(idx & (KREAL - 1));
        long r0 = idx >> 10;
        int m = (int)(r0 & 127);
        long r1 = r0 >> 7;
        int hl = (int)(r1 & 1);
        int p  = (int)((r1 >> 1) & 1);
        int l  = (int)(r1 >> 2);
        __nv_bfloat16 out = __float2bfloat16(0.f);
        if (l == 0 && p == 1 && k < 512) {
            float v = x[((size_t)m * Tv) * Hv + k];
            __nv_bfloat16 hi = __float2bfloat16(v);
            out = (hl == 0) ? hi : __float2bfloat16(v - __bfloat162float(hi));
        }
        (&g_A[0][0][0][0][0])[idx] = out;
    }
}

// ---------------- main persistent HMMA kernel ----------------
__global__ void __launch_bounds__(BLK, 1) gru_tc(
    const float* __restrict__ x,
    const float* __restrict__ bih0, const float* __restrict__ bhh0,
    const float* __restrict__ bih1, const float* __restrict__ bhh1,
    const float* __restrict__ bih2, const float* __restrict__ bhh2,
    float* __restrict__ y)
{
    extern __shared__ char smem[];
    const uint32_t sm0 = smem_u32(smem) + 512;
    const int tid  = threadIdx.x;
    const int lane = tid & 31;
    const int wid  = tid >> 5;
    const int mw   = wid >> 2;          // 0..3
    const int nw   = wid & 3;           // 0..3
    const int l     = blockIdx.x >> 5;
    const int li    = (blockIdx.x >> 1) & 15;
    const int mhalf = blockIdx.x & 1;
    const int J0    = li * 32;

    const float* bihL = (l == 0) ? bih0 : (l == 1) ? bih1 : bih2;
    const float* bhhL = (l == 0) ? bhh0 : (l == 1) ? bhh1 : bhh2;

    float* sb = (float*)smem;
    if (tid < 32) {
        int j = J0 + tid;
        sb[tid]      = bihL[0 * Hv + j] + bhhL[0 * Hv + j];
        sb[32 + tid] = bihL[1 * Hv + j] + bhhL[1 * Hv + j];
        sb[64 + tid] = bihL[2 * Hv + j];
        sb[96 + tid] = bhhL[2 * Hv + j];
    }
    __syncthreads();

    const uint32_t aoff = (uint32_t)((16 * mw + (lane & 15)) * AROWB + (lane >> 4) * 16);
    const uint32_t boff0 = (uint32_t)((32 * (lane >> 4) + 8 * nw + (lane & 7)) * AROWB
                                      + ((lane >> 3) & 1) * 16);
    const uint32_t boff1 = boff0 + 64u * AROWB;

    const __nv_bfloat16* Bg = &g_B[l][li][0][0][0];
    const unsigned base = *((volatile unsigned*)&g_phase);

    const int u0 = 8 * nw + (lane & 3) * 2;
    const int m0 = 64 * mhalf + 16 * mw + (lane >> 2);
    const int j0 = J0 + u0;
    float hloc[4] = {0.f, 0.f, 0.f, 0.f};

    // W staging: skip structurally-zero gate rows (i_n rows 64-95 in h-half
    // chunks, h_n rows 96-127 in x-half chunks).
    auto stageW = [&](int s) {
        const bool xh = (s < 8);
        uint32_t buf = sm0 + (uint32_t)(s & 3) * STAGE_BYTES;
        const char* gbB = (const char*)Bg + (size_t)s * (KCH * 2);
#pragma unroll
        for (int i2 = 0; i2 < 4; ++i2) {
            int i = tid + i2 * BLK;           // 0..2047
            int c16 = i & 7;
            int rb = i >> 3;                  // 0..255
            int hl = rb >> 7, r = rb & 127;
            int gate = r >> 5;
            bool skip = xh ? (gate == 3) : (gate == 2);
            if (!skip)
                cp16(buf + (uint32_t)(OFF_WHI + hl * 18432 + r * AROWB + c16 * 16),
                     gbB + ((size_t)hl * 128 + r) * (KREAL * 2) + c16 * 16);
        }
    };

#pragma unroll 1
    for (int k = 0; k < NTICK; ++k) {
        const int t = k - l;
        const bool active = (t >= 0) && (t < Tv);
        const int rp = (k + 1) & 1;
        const int wp = k & 1;

        if (active) {
            const __nv_bfloat16* Ag = &g_A[l][rp][0][0][0];

            auto stageA = [&](int s) {
                uint32_t buf = sm0 + (uint32_t)(s & 3) * STAGE_BYTES;
                const char* gaB = (const char*)Ag + (size_t)s * (KCH * 2);
#pragma unroll
                for (int i2 = 0; i2 < 2; ++i2) {
                    int i = tid + i2 * BLK;       // 0..1023
                    int c16 = i & 7;
                    int rb = i >> 3;              // 0..127
                    int hl = rb >> 6, r = rb & 63;
                    cp16(buf + (uint32_t)(hl * OFF_ALO + r * AROWB + c16 * 16),
                         gaB + ((size_t)hl * 128 + 64 * mhalf + r) * (KREAL * 2) + c16 * 16);
                }
            };

            if (l == 0 && k == 0) { stageW(0); stageW(1); stageW(2); }
            stageA(0); asm volatile("cp.async.commit_group;");
            stageA(1); asm volatile("cp.async.commit_group;");
            stageA(2); asm volatile("cp.async.commit_group;");

            float2 xm[2];
            if (l == 2) {
                xm[0] = *(const float2*)(x + ((size_t)m0 * Tv + t) * Hv + j0);
                xm[1] = *(const float2*)(x + ((size_t)(m0 + 8) * Tv + t) * Hv + j0);
            }

            float acc[4][4];
#pragma unroll
            for (int g = 0; g < 4; ++g)
#pragma unroll
                for (int e = 0; e < 4; ++e) acc[g][e] = 0.f;

// One chunk iteration; XH is a compile-time literal selecting which
// structurally-zero gate to skip (x-half: h_n=acc[3]; h-half: i_n=acc[2]).
#define DO_CHUNK(cc, XH) do { \
    const int rem = NCHUNK - 1 - (cc); \
    if (rem >= 2)      asm volatile("cp.async.wait_group 2;"); \
    else if (rem == 1) asm volatile("cp.async.wait_group 1;"); \
    else               asm volatile("cp.async.wait_group 0;"); \
    __syncthreads(); \
    if ((cc) + 3 < NCHUNK) { \
        stageW((cc) + 3); stageA((cc) + 3); \
        asm volatile("cp.async.commit_group;"); \
    } \
    const uint32_t st = sm0 + (uint32_t)((cc) & 3) * STAGE_BYTES; \
    _Pragma("unroll") \
    for (int ks = 0; ks < KCH / 16; ++ks) { \
        const uint32_t kb = (uint32_t)(ks * 32); \
        uint32_t ahi[4], alo[4]; \
        LDMX4(ahi, st + aoff + kb); \
        LDMX4(alo, st + OFF_ALO + aoff + kb); \
        uint32_t wh0[4], wh1[4], wl0[4], wl1[4]; \
        LDMX4(wh0, st + OFF_WHI + boff0 + kb); \
        LDMX4(wh1, st + OFF_WHI + boff1 + kb); \
        LDMX4(wl0, st + OFF_WHI + 18432 + boff0 + kb); \
        LDMX4(wl1, st + OFF_WHI + 18432 + boff1 + kb); \
        MMA16816(acc[0], ahi, wh0[0], wh0[1]); \
        MMA16816(acc[1], ahi, wh0[2], wh0[3]); \
        MMA16816(acc[0], alo, wh0[0], wh0[1]); \
        MMA16816(acc[1], alo, wh0[2], wh0[3]); \
        MMA16816(acc[0], ahi, wl0[0], wl0[1]); \
        MMA16816(acc[1], ahi, wl0[2], wl0[3]); \
        if (XH) { \
            MMA16816(acc[2], ahi, wh1[0], wh1[1]); \
            MMA16816(acc[2], alo, wh1[0], wh1[1]); \
            MMA16816(acc[2], ahi, wl1[0], wl1[1]); \
        } else { \
            MMA16816(acc[3], ahi, wh1[2], wh1[3]); \
            MMA16816(acc[3], alo, wh1[2], wh1[3]); \
            MMA16816(acc[3], ahi, wl1[2], wl1[3]); \
        } \
    } \
} while (0)

#pragma unroll 1
            for (int c = 0; c < 8; ++c) DO_CHUNK(c, true);
#pragma unroll 1
            for (int c = 8; c < NCHUNK; ++c) DO_CHUNK(c, false);
#undef DO_CHUNK

            if ((k + 1 - l) >= 0 && (k + 1 - l) < Tv) {
                stageW(0); stageW(1); stageW(2);
            }

            // ---------- epilogue ----------
#pragma unroll
            for (int rr = 0; rr < 2; ++rr) {
                const int m = m0 + 8 * rr;
                float hv[2];
#pragma unroll
                for (int up = 0; up < 2; ++up) {
                    const int u = u0 + up, e = 2 * rr + up;
                    float r = sigf(acc[0][e] + sb[u]);
                    float z = sigf(acc[1][e] + sb[32 + u]);
                    float n = tanh_fast(acc[2][e] + sb[64 + u]
                                        + r * (acc[3][e] + sb[96 + u]));
                    hv[up] = (1.f - z) * n + z * hloc[rr * 2 + up];
                }
                if (l == 2) {
                    if (xm[rr].x == 0.f) hv[0] = 0.f;
                    if (xm[rr].y == 0.f) hv[1] = 0.f;
                    *(float2*)(y + ((size_t)m * Tv + t) * Hv + j0) =
                        make_float2(hv[0], hv[1]);
                }
                hloc[rr * 2 + 0] = hv[0];
                hloc[rr * 2 + 1] = hv[1];

                __nv_bfloat16 h0 = __float2bfloat16(hv[0]);
                __nv_bfloat16 h1 = __float2bfloat16(hv[1]);
                __nv_bfloat16 L0 = __float2bfloat16(hv[0] - __bfloat162float(h0));
                __nv_bfloat16 L1 = __float2bfloat16(hv[1] - __bfloat162float(h1));
                unsigned hp32 = (unsigned)__bfloat16_as_ushort(h0)
                              | ((unsigned)__bfloat16_as_ushort(h1) << 16);
                unsigned lp32 = (unsigned)__bfloat16_as_ushort(L0)
                              | ((unsigned)__bfloat16_as_ushort(L1) << 16);
                *(unsigned*)&g_A[l][wp][0][m][512 + j0] = hp32;   // self h-half
                *(unsigned*)&g_A[l][wp][1][m][512 + j0] = lp32;
                if (l < 2) {                                      // next-layer x-half
                    *(unsigned*)&g_A[l + 1][wp][0][m][j0] = hp32;
                    *(unsigned*)&g_A[l + 1][wp][1][m][j0] = lp32;
                }
            }
        } else {
            if ((k + 1 - l) >= 0 && (k + 1 - l) < Tv) {
                stageW(0); stageW(1); stageW(2);
            }
        }

        // layer-0 CTAs stage x_{k+1} into next parity's A0 x-region
        if (l == 0 && (k + 1) < Tv && tid < 256) {
            const int row = tid >> 2;
            const int kc0 = (tid & 3) * 8;
            const int m = 64 * mhalf + row;
            const float* xs = x + ((size_t)m * Tv + (k + 1)) * Hv + 32 * li + kc0;
            unsigned hp[4], lp[4];
#pragma unroll
            for (int q = 0; q < 4; ++q) {
                float v0 = xs[2 * q], v1 = xs[2 * q + 1];
                __nv_bfloat16 h0 = __float2bfloat16(v0);
                __nv_bfloat16 h1 = __float2bfloat16(v1);
                __nv_bfloat16 L0 = __float2bfloat16(v0 - __bfloat162float(h0));
                __nv_bfloat16 L1 = __float2bfloat16(v1 - __bfloat162float(h1));
                hp[q] = (unsigned)__bfloat16_as_ushort(h0)
                      | ((unsigned)__bfloat16_as_ushort(h1) << 16);
                lp[q] = (unsigned)__bfloat16_as_ushort(L0)
                      | ((unsigned)__bfloat16_as_ushort(L1) << 16);
            }
            *(uint4*)&g_A[0][wp][0][m][32 * li + kc0] =
                make_uint4(hp[0], hp[1], hp[2], hp[3]);
            *(uint4*)&g_A[0][wp][1][m][32 * li + kc0] =
                make_uint4(lp[0], lp[1], lp[2], lp[3]);
        }

        gsync(base + 1 + k);
    }
}

extern "C" void kernel_launch(void* const* d_in, const int* in_sizes, int n_in,
                              void* d_out, int out_size) {
    (void)in_sizes; (void)n_in; (void)out_size;
    const float* x = (const float*)d_in[0];
    gru_prep<<<256, 256>>>(x,
        (const float*)d_in[1], (const float*)d_in[2],
        (const float*)d_in[5], (const float*)d_in[6],
        (const float*)d_in[9], (const float*)d_in[10]);
    cudaFuncSetAttribute(gru_tc, cudaFuncAttributeMaxDynamicSharedMemorySize, SMEM_TOTAL);
    gru_tc<<<NCTA, BLK, SMEM_TOTAL>>>(x,
        (const float*)d_in[3],  (const float*)d_in[4],
        (const float*)d_in[7],  (const float*)d_in[8],
        (const float*)d_in[11], (const float*)d_in[12],
        (float*)d_out);
}

// round 14
// speedup vs baseline: 1.6637x; 1.0612x over previous
#include <cuda_runtime.h>
#include <cuda_bf16.h>
#include <cstdint>

// 3-layer GRU (r,z,n), B=128, T=512, H=512, fp32 — bf16 hi/lo mma.sync, v8.
// = v7 (KCH=128, 8 chunks, 2-stage ring, compact 96-row W staging, gate-sparse
// 9 MMA/ks) with the pipeline race FIXED: per chunk the order is
//   cp.async.wait_group 0 (own groups) -> __syncthreads (ALL threads' data
//   visible; all warps done with previous chunk) -> stage c+1 -> compute c.
// v7 had wait AFTER the barrier, so warps read tiles other threads were still
// filling (rel_err 6e-3 = intermittent hi-only arithmetic).
// Wavefront: tick k -> layer l computes t = k - l; one grid barrier per tick.
// 96 CTAs = 3 layers x 16 col-tiles x 2 batch halves; 16 warps (4Mx4N).
// D[64,128] = sum over K=1024 of a_hi*w_hi + a_lo*w_hi + a_hi*w_lo.

#define Bv 128
#define Tv 512
#define Hv 512
#define NLAYER 3
#define CPL 16
#define NCTA 96
#define BLK 512
#define NTICK (Tv + 2)
#define KREAL 1024
#define KCH 128
#define NCHUNK (KREAL / KCH)   // 8
#define AROWB 272              // (KCH+8)*2 bytes per smem row
#define OFF_ALO 17408          // 64*272
#define OFF_WHI 34816          // 2*17408
#define WPLANE 26112           // 96*272
#define OFF_WLO (OFF_WHI + WPLANE)
#define STAGE_BYTES (OFF_WLO + WPLANE)   // 87040
#define SMEM_TOTAL (512 + 2 * STAGE_BYTES)

__device__ __nv_bfloat16 g_B[NLAYER][CPL][2][128][KREAL];  // [hl][n][k]
__device__ __nv_bfloat16 g_A[NLAYER][2][2][Bv][KREAL];     // [parity][hl][m][k]
__device__ unsigned g_count = 0;
__device__ unsigned g_phase = 0;

__device__ __forceinline__ uint32_t smem_u32(const void* p) {
    uint32_t a;
    asm("{ .reg .u64 t; cvta.to.shared.u64 t, %1; cvt.u32.u64 %0, t; }" : "=r"(a) : "l"(p));
    return a;
}
__device__ __forceinline__ void cp16(uint32_t s, const void* g) {
    asm volatile("cp.async.cg.shared.global [%0], [%1], 16;" :: "r"(s), "l"(g));
}
__device__ __forceinline__ float sigf(float x) { return 1.f / (1.f + __expf(-x)); }
__device__ __forceinline__ float tanh_fast(float x) {
    x = fminf(fmaxf(x, -15.f), 15.f);
    float t = __expf(2.f * x);
    return (t - 1.f) / (t + 1.f);
}
__device__ __forceinline__ void gsync(unsigned target) {
    __syncthreads();
    if (threadIdx.x == 0) {
        __threadfence();
        unsigned a = atomicAdd(&g_count, 1u);
        if (a == NCTA - 1) {
            g_count = 0u;
            __threadfence();
            atomicAdd(&g_phase, 1u);
        } else {
            while (*((volatile unsigned*)&g_phase) < target) __nanosleep(32);
        }
    }
    __syncthreads();
}

#define MMA16816(d, a, b0, b1) \
    asm volatile("mma.sync.aligned.m16n8k16.row.col.f32.bf16.bf16.f32 " \
        "{%0,%1,%2,%3}, {%4,%5,%6,%7}, {%8,%9}, {%0,%1,%2,%3};" \
        : "+f"((d)[0]), "+f"((d)[1]), "+f"((d)[2]), "+f"((d)[3]) \
        : "r"((a)[0]), "r"((a)[1]), "r"((a)[2]), "r"((a)[3]), \
          "r"(b0), "r"(b1))

#define LDMX4(r, a) \
    asm volatile("ldmatrix.sync.aligned.m8n8.x4.shared.b16 {%0,%1,%2,%3}, [%4];" \
        : "=r"((r)[0]), "=r"((r)[1]), "=r"((r)[2]), "=r"((r)[3]) : "r"(a))
#define LDMX2(r, a) \
    asm volatile("ldmatrix.sync.aligned.m8n8.x2.shared.b16 {%0,%1}, [%2];" \
        : "=r"((r)[0]), "=r"((r)[1]) : "r"(a))

// ---------------- prep ----------------
__global__ void gru_prep(const float* __restrict__ x,
    const float* __restrict__ Wih0, const float* __restrict__ Whh0,
    const float* __restrict__ Wih1, const float* __restrict__ Whh1,
    const float* __restrict__ Wih2, const float* __restrict__ Whh2)
{
    const float* WI[3] = {Wih0, Wih1, Wih2};
    const float* WH[3] = {Whh0, Whh1, Whh2};
    const long gsz = (long)gridDim.x * blockDim.x;
    const long gid = (long)blockIdx.x * blockDim.x + threadIdx.x;

    const long BTOT = (long)NLAYER * CPL * 2 * 128 * KREAL;
    for (long idx = gid; idx < BTOT; idx += gsz) {
        int k   = (int)(idx & (KREAL - 1));
        long r0 = idx >> 10;
        int n   = (int)(r0 & 127);
        long r1 = r0 >> 7;
        int hl  = (int)(r1 & 1);
        long r2 = r1 >> 1;
        int li  = (int)(r2 % CPL);
        int l   = (int)(r2 / CPL);
        int gate = n >> 5, u = n & 31, j = li * 32 + u;
        int half = k >> 9, kk = k & 511;
        float wv = 0.f;
        if (half == 0) {
            if (gate < 3) wv = WI[l][(size_t)(gate * Hv + j) * Hv + kk];
        } else {
            if (gate == 0)      wv = WH[l][(size_t)(0 * Hv + j) * Hv + kk];
            else if (gate == 1) wv = WH[l][(size_t)(1 * Hv + j) * Hv + kk];
            else if (gate == 3) wv = WH[l][(size_t)(2 * Hv + j) * Hv + kk];
        }
        __nv_bfloat16 hi = __float2bfloat16(wv);
        (&g_B[0][0][0][0][0])[idx] = (hl == 0) ? hi
            : __float2bfloat16(wv - __bfloat162float(hi));
    }
    const long ATOT = (long)NLAYER * 2 * 2 * Bv * KREAL;
    for (long idx = gid; idx < ATOT; idx += gsz) {
        int k = (int)(idx & (KREAL - 1));
        long r0 = idx >> 10;
        int m = (int)(r0 & 127);
        long r1 = r0 >> 7;
        int hl = (int)(r1 & 1);
        int p  = (int)((r1 >> 1) & 1);
        int l  = (int)(r1 >> 2);
        __nv_bfloat16 out = __float2bfloat16(0.f);
        if (l == 0 && p == 1 && k < 512) {
            float v = x[((size_t)m * Tv) * Hv + k];
            __nv_bfloat16 hi = __float2bfloat16(v);
            out = (hl == 0) ? hi : __float2bfloat16(v - __bfloat162float(hi));
        }
        (&g_A[0][0][0][0][0])[idx] = out;
    }
}

// ---------------- main persistent HMMA kernel ----------------
__global__ void __launch_bounds__(BLK, 1) gru_tc(
    const float* __restrict__ x,
    const float* __restrict__ bih0, const float* __restrict__ bhh0,
    const float* __restrict__ bih1, const float* __restrict__ bhh1,
    const float* __restrict__ bih2, const float* __restrict__ bhh2,
    float* __restrict__ y)
{
    extern __shared__ char smem[];
    const uint32_t sm0 = smem_u32(smem) + 512;
    const int tid  = threadIdx.x;
    const int lane = tid & 31;
    const int wid  = tid >> 5;
    const int mw   = wid >> 2;          // 0..3
    const int nw   = wid & 3;           // 0..3
    const int l     = blockIdx.x >> 5;
    const int li    = (blockIdx.x >> 1) & 15;
    const int mhalf = blockIdx.x & 1;
    const int J0    = li * 32;

    const float* bihL = (l == 0) ? bih0 : (l == 1) ? bih1 : bih2;
    const float* bhhL = (l == 0) ? bhh0 : (l == 1) ? bhh1 : bhh2;

    float* sb = (float*)smem;
    if (tid < 32) {
        int j = J0 + tid;
        sb[tid]      = bihL[0 * Hv + j] + bhhL[0 * Hv + j];
        sb[32 + tid] = bihL[1 * Hv + j] + bhhL[1 * Hv + j];
        sb[64 + tid] = bihL[2 * Hv + j];
        sb[96 + tid] = bhhL[2 * Hv + j];
    }
    __syncthreads();

    const uint32_t aoff = (uint32_t)((16 * mw + (lane & 15)) * AROWB + (lane >> 4) * 16);
    const uint32_t boff0 = (uint32_t)((32 * (lane >> 4) + 8 * nw + (lane & 7)) * AROWB
                                      + ((lane >> 3) & 1) * 16);
    const uint32_t boffG = (uint32_t)((64 + 8 * nw + (lane & 7)) * AROWB
                                      + ((lane >> 3) & 1) * 16);   // x2, lanes 0-15

    const __nv_bfloat16* Bg = &g_B[l][li][0][0][0];
    const unsigned base = *((volatile unsigned*)&g_phase);

    const int u0 = 8 * nw + (lane & 3) * 2;
    const int m0 = 64 * mhalf + 16 * mw + (lane >> 2);
    const int j0 = J0 + u0;
    float hloc[4] = {0.f, 0.f, 0.f, 0.f};

    // Compact W staging: only 96 live rows/plane (gates 0,1 + live n-gate).
    auto stageW = [&](int s) {
        const bool xh = (s < 4);
        uint32_t buf = sm0 + (uint32_t)(s & 1) * STAGE_BYTES;
        const char* gbB = (const char*)Bg + (size_t)s * (KCH * 2);
#pragma unroll
        for (int i2 = 0; i2 < 6; ++i2) {
            int i = tid + i2 * BLK;           // 0..3071
            int c16 = i & 15;
            int cr = i >> 4;                  // 0..191
            int hl = (cr >= 96) ? 1 : 0;
            int r  = cr - hl * 96;            // 0..95 compact
            int orig = (r < 64) ? r : (xh ? r : r + 32);
            cp16(buf + (uint32_t)(OFF_WHI + hl * WPLANE + r * AROWB + c16 * 16),
                 gbB + ((size_t)hl * 128 + orig) * (KREAL * 2) + c16 * 16);
        }
    };

#pragma unroll 1
    for (int k = 0; k < NTICK; ++k) {
        const int t = k - l;
        const bool active = (t >= 0) && (t < Tv);
        const int rp = (k + 1) & 1;
        const int wp = k & 1;
        const bool wpre = !(l == 0 && k == 0);   // W0,W1 staged before barrier?
        const bool nextActive = ((k + 1 - l) >= 0) && ((k + 1 - l) < Tv);

        if (active) {
            const __nv_bfloat16* Ag = &g_A[l][rp][0][0][0];

            auto stageA = [&](int s) {
                uint32_t buf = sm0 + (uint32_t)(s & 1) * STAGE_BYTES;
                const char* gaB = (const char*)Ag + (size_t)s * (KCH * 2);
#pragma unroll
                for (int i2 = 0; i2 < 4; ++i2) {
                    int i = tid + i2 * BLK;       // 0..2047
                    int c16 = i & 15;
                    int ar = i >> 4;              // 0..127
                    int hl = ar >> 6, r = ar & 63;
                    cp16(buf + (uint32_t)(hl * OFF_ALO + r * AROWB + c16 * 16),
                         gaB + ((size_t)hl * 128 + 64 * mhalf + r) * (KREAL * 2) + c16 * 16);
                }
            };

            // prologue: chunk 0 (W0,W1 prefetched cross-tick when warm)
            if (!wpre) stageW(0);
            stageA(0);
            asm volatile("cp.async.commit_group;");

            float2 xm[2];
            if (l == 2) {
                xm[0] = *(const float2*)(x + ((size_t)m0 * Tv + t) * Hv + j0);
                xm[1] = *(const float2*)(x + ((size_t)(m0 + 8) * Tv + t) * Hv + j0);
            }

            float acc[4][4];
#pragma unroll
            for (int g = 0; g < 4; ++g)
#pragma unroll
                for (int e = 0; e < 4; ++e) acc[g][e] = 0.f;

// FIXED ordering: wait own groups (chunk cc landed for this thread), then
// __syncthreads (all threads' chunk-cc data visible, all warps done with
// chunk cc-1 so its buffer may be overwritten), then stage cc+1, then compute.
#define DO_CHUNK(cc, XH) do { \
    asm volatile("cp.async.wait_group 0;"); \
    __syncthreads(); \
    if ((cc) + 1 < NCHUNK) { \
        if (!(wpre && (cc) == 0)) stageW((cc) + 1); \
        stageA((cc) + 1); \
        asm volatile("cp.async.commit_group;"); \
    } \
    const uint32_t st = sm0 + (uint32_t)((cc) & 1) * STAGE_BYTES; \
    _Pragma("unroll") \
    for (int ks = 0; ks < KCH / 16; ++ks) { \
        const uint32_t kb = (uint32_t)(ks * 32); \
        uint32_t ahi[4], alo[4]; \
        LDMX4(ahi, st + aoff + kb); \
        LDMX4(alo, st + OFF_ALO + aoff + kb); \
        uint32_t wh0[4], wl0[4], whg[2], wlg[2]; \
        LDMX4(wh0, st + OFF_WHI + boff0 + kb); \
        LDMX4(wl0, st + OFF_WLO + boff0 + kb); \
        LDMX2(whg, st + OFF_WHI + boffG + kb); \
        LDMX2(wlg, st + OFF_WLO + boffG + kb); \
        MMA16816(acc[0], ahi, wh0[0], wh0[1]); \
        MMA16816(acc[1], ahi, wh0[2], wh0[3]); \
        MMA16816(acc[0], alo, wh0[0], wh0[1]); \
        MMA16816(acc[1], alo, wh0[2], wh0[3]); \
        MMA16816(acc[0], ahi, wl0[0], wl0[1]); \
        MMA16816(acc[1], ahi, wl0[2], wl0[3]); \
        if (XH) { \
            MMA16816(acc[2], ahi, whg[0], whg[1]); \
            MMA16816(acc[2], alo, whg[0], whg[1]); \
            MMA16816(acc[2], ahi, wlg[0], wlg[1]); \
        } else { \
            MMA16816(acc[3], ahi, whg[0], whg[1]); \
            MMA16816(acc[3], alo, whg[0], whg[1]); \
            MMA16816(acc[3], ahi, wlg[0], wlg[1]); \
        } \
    } \
} while (0)

#pragma unroll 1
            for (int c = 0; c < 4; ++c) DO_CHUNK(c, true);
#pragma unroll 1
            for (int c = 4; c < NCHUNK; ++c) DO_CHUNK(c, false);
#undef DO_CHUNK

            // all warps done reading both buffers, then prefetch next tick's W
            __syncthreads();
            if (nextActive) {
                stageW(0); asm volatile("cp.async.commit_group;");
                stageW(1); asm volatile("cp.async.commit_group;");
            }

            // ---------- epilogue ----------
#pragma unroll
            for (int rr = 0; rr < 2; ++rr) {
                const int m = m0 + 8 * rr;
                float hv[2];
#pragma unroll
                for (int up = 0; up < 2; ++up) {
                    const int u = u0 + up, e = 2 * rr + up;
                    float r = sigf(acc[0][e] + sb[u]);
                    float z = sigf(acc[1][e] + sb[32 + u]);
                    float n = tanh_fast(acc[2][e] + sb[64 + u]
                                        + r * (acc[3][e] + sb[96 + u]));
                    hv[up] = (1.f - z) * n + z * hloc[rr * 2 + up];
                }
                if (l == 2) {
                    if (xm[rr].x == 0.f) hv[0] = 0.f;
                    if (xm[rr].y == 0.f) hv[1] = 0.f;
                    *(float2*)(y + ((size_t)m * Tv + t) * Hv + j0) =
                        make_float2(hv[0], hv[1]);
                }
                hloc[rr * 2 + 0] = hv[0];
                hloc[rr * 2 + 1] = hv[1];

                __nv_bfloat16 h0 = __float2bfloat16(hv[0]);
                __nv_bfloat16 h1 = __float2bfloat16(hv[1]);
                __nv_bfloat16 L0 = __float2bfloat16(hv[0] - __bfloat162float(h0));
                __nv_bfloat16 L1 = __float2bfloat16(hv[1] - __bfloat162float(h1));
                unsigned hp32 = (unsigned)__bfloat16_as_ushort(h0)
                              | ((unsigned)__bfloat16_as_ushort(h1) << 16);
                unsigned lp32 = (unsigned)__bfloat16_as_ushort(L0)
                              | ((unsigned)__bfloat16_as_ushort(L1) << 16);
                *(unsigned*)&g_A[l][wp][0][m][512 + j0] = hp32;   // self h-half
                *(unsigned*)&g_A[l][wp][1][m][512 + j0] = lp32;
                if (l < 2) {                                      // next-layer x-half
                    *(unsigned*)&g_A[l + 1][wp][0][m][j0] = hp32;
                    *(unsigned*)&g_A[l + 1][wp][1][m][j0] = lp32;
                }
            }
        } else {
            if (nextActive) {
                stageW(0); asm volatile("cp.async.commit_group;");
                stageW(1); asm volatile("cp.async.commit_group;");
            }
        }

        // layer-0 CTAs stage x_{k+1} into next parity's A0 x-region
        if (l == 0 && (k + 1) < Tv && tid < 256) {
            const int row = tid >> 2;
            const int kc0 = (tid & 3) * 8;
            const int m = 64 * mhalf + row;
            const float* xs = x + ((size_t)m * Tv + (k + 1)) * Hv + 32 * li + kc0;
            unsigned hp[4], lp[4];
#pragma unroll
            for (int q = 0; q < 4; ++q) {
                float v0 = xs[2 * q], v1 = xs[2 * q + 1];
                __nv_bfloat16 h0 = __float2bfloat16(v0);
                __nv_bfloat16 h1 = __float2bfloat16(v1);
                __nv_bfloat16 L0 = __float2bfloat16(v0 - __bfloat162float(h0));
                __nv_bfloat16 L1 = __float2bfloat16(v1 - __bfloat162float(h1));
                hp[q] = (unsigned)__bfloat16_as_ushort(h0)
                      | ((unsigned)__bfloat16_as_ushort(h1) << 16);
                lp[q] = (unsigned)__bfloat16_as_ushort(L0)
                      | ((unsigned)__bfloat16_as_ushort(L1) << 16);
            }
            *(uint4*)&g_A[0][wp][0][m][32 * li + kc0] =
                make_uint4(hp[0], hp[1], hp[2], hp[3]);
            *(uint4*)&g_A[0][wp][1][m][32 * li + kc0] =
                make_uint4(lp[0], lp[1], lp[2], lp[3]);
        }

        gsync(base + 1 + k);
    }
}

extern "C" void kernel_launch(void* const* d_in, const int* in_sizes, int n_in,
                              void* d_out, int out_size) {
    (void)in_sizes; (void)n_in; (void)out_size;
    const float* x = (const float*)d_in[0];
    gru_prep<<<256, 256>>>(x,
        (const float*)d_in[1], (const float*)d_in[2],
        (const float*)d_in[5], (const float*)d_in[6],
        (const float*)d_in[9], (const float*)d_in[10]);
    cudaFuncSetAttribute(gru_tc, cudaFuncAttributeMaxDynamicSharedMemorySize, SMEM_TOTAL);
    gru_tc<<<NCTA, BLK, SMEM_TOTAL>>>(x,
        (const float*)d_in[3],  (const float*)d_in[4],
        (const float*)d_in[7],  (const float*)d_in[8],
        (const float*)d_in[11], (const float*)d_in[12],
        (float*)d_out);
}